// round 1
// baseline (speedup 1.0000x reference)
#include <cuda_runtime.h>
#include <math.h>
#include <float.h>

typedef unsigned long long u64;

static constexpr int B_  = 128;
static constexpr int T_  = 8;
static constexpr int E_  = 52;
static constexpr int S_  = 2048;
static constexpr int R_  = 512;
static constexpr int G3_ = 1536;   // 3*R

static constexpr int SPLIT = 32;        // s-dimension split for pooling
static constexpr int SCH   = S_ / SPLIT; // 64 rows per pooling block

// GEMM tiling
static constexpr int KS = 8;            // k-split
static constexpr int KC = R_ / KS;      // 64 k per block
static constexpr int KT = 16;           // k per smem tile
static constexpr int RB = 32;           // rows per block

// ---------------- device scratch (no allocations allowed) ----------------
__device__ __align__(16) float g_part[B_ * SPLIT * R_];    // pooling partial maxes (8 MB)
__device__ float g_a[B_ * 4];                              // code_pool @ W_fc_pool^T
__device__ __align__(16) float g_hT[2][R_ * B_];           // hidden state, transposed [j][b], ping-pong
__device__ __align__(16) float g_bmiT[E_ * B_];            // bmi vector, transposed [e][b]
__device__ __align__(16) float g_gx[T_ * G3_ * B_];        // precomputed x-part of gi (+b_ih), [t][row][b]
__device__ __align__(16) u64   g_Wd[R_ * G3_];             // W_hh transposed + duplicated: [k][row] = (w,w)
__device__ __align__(16) float g_gpart[KS * G3_ * B_];     // k-split GEMM partials

__device__ __forceinline__ float sigmoidf_(float x) { return 1.f / (1.f + expf(-x)); }

// ---------------- 1. ragged max-pool, partial ----------------
__global__ void k_pool(const float* __restrict__ enc, const int* __restrict__ enc_len) {
    int sp = blockIdx.x, b = blockIdx.y, tid = threadIdx.x;  // 128 threads
    int len = enc_len[b];
    int s0 = sp * SCH;
    int s1 = min(s0 + SCH, len);
    float4 m = make_float4(-FLT_MAX, -FLT_MAX, -FLT_MAX, -FLT_MAX);
    const float4* base = reinterpret_cast<const float4*>(enc + (size_t)b * S_ * R_) + tid;
    int s = s0;
    for (; s + 4 <= s1; s += 4) {
        float4 v0 = base[(size_t)(s + 0) * (R_ / 4)];
        float4 v1 = base[(size_t)(s + 1) * (R_ / 4)];
        float4 v2 = base[(size_t)(s + 2) * (R_ / 4)];
        float4 v3 = base[(size_t)(s + 3) * (R_ / 4)];
        m.x = fmaxf(m.x, fmaxf(fmaxf(v0.x, v1.x), fmaxf(v2.x, v3.x)));
        m.y = fmaxf(m.y, fmaxf(fmaxf(v0.y, v1.y), fmaxf(v2.y, v3.y)));
        m.z = fmaxf(m.z, fmaxf(fmaxf(v0.z, v1.z), fmaxf(v2.z, v3.z)));
        m.w = fmaxf(m.w, fmaxf(fmaxf(v0.w, v1.w), fmaxf(v2.w, v3.w)));
    }
    for (; s < s1; s++) {
        float4 v = base[(size_t)s * (R_ / 4)];
        m.x = fmaxf(m.x, v.x); m.y = fmaxf(m.y, v.y);
        m.z = fmaxf(m.z, v.z); m.w = fmaxf(m.w, v.w);
    }
    reinterpret_cast<float4*>(g_part)[(b * SPLIT + sp) * (R_ / 4) + tid] = m;
}

// ---------------- 2. reduce partials -> code_pool, then a = code @ W_fc^T ----------------
__global__ void k_reduce_a(const float* __restrict__ Wfc) {
    int b = blockIdx.x, tid = threadIdx.x;  // 128 threads
    float4 m = make_float4(-FLT_MAX, -FLT_MAX, -FLT_MAX, -FLT_MAX);
    const float4* pp = reinterpret_cast<const float4*>(g_part) + (size_t)b * SPLIT * (R_ / 4) + tid;
    #pragma unroll 8
    for (int sp = 0; sp < SPLIT; sp++) {
        float4 v = pp[sp * (R_ / 4)];
        m.x = fmaxf(m.x, v.x); m.y = fmaxf(m.y, v.y);
        m.z = fmaxf(m.z, v.z); m.w = fmaxf(m.w, v.w);
    }
    __shared__ float code[R_];
    reinterpret_cast<float4*>(code)[tid] = m;
    __syncthreads();
    float p[4] = {0.f, 0.f, 0.f, 0.f};
    int r0 = tid * 4;
    #pragma unroll
    for (int i = 0; i < 4; i++) {
        float c = code[r0 + i];
        p[0] += c * Wfc[0 * R_ + r0 + i];
        p[1] += c * Wfc[1 * R_ + r0 + i];
        p[2] += c * Wfc[2 * R_ + r0 + i];
        p[3] += c * Wfc[3 * R_ + r0 + i];
    }
    __shared__ float red[4][128];
    #pragma unroll
    for (int l = 0; l < 4; l++) red[l][tid] = p[l];
    __syncthreads();
    int w = tid >> 5, lane = tid & 31;  // w in 0..3 always (128 threads)
    float sacc = red[w][lane] + red[w][lane + 32] + red[w][lane + 64] + red[w][lane + 96];
    #pragma unroll
    for (int off = 16; off; off >>= 1) sacc += __shfl_down_sync(0xffffffffu, sacc, off);
    if (lane == 0) g_a[b * 4 + w] = sacc;
}

// ---------------- 3. transpose h_n into g_hT[0] ----------------
__global__ void k_hT(const float* __restrict__ hn) {
    int idx = blockIdx.x * blockDim.x + threadIdx.x;  // 65536 total
    int b = idx >> 9, j = idx & (R_ - 1);
    g_hT[0][j * B_ + b] = hn[b * R_ + j];
}

// ---------------- 4. build duplicated/transposed W_hh ----------------
__global__ void k_wd(const float* __restrict__ Whh) {
    int idx = blockIdx.x * blockDim.x + threadIdx.x;  // 512*1536
    if (idx >= R_ * G3_) return;
    int k = idx / G3_, row = idx - k * G3_;
    float w = Whh[row * R_ + k];
    unsigned u = __float_as_uint(w);
    g_Wd[idx] = ((u64)u << 32) | (u64)u;
}

// ---------------- 5. precompute gx[t][row][b] = b_ih[row] + x[b,t]·W_ih[row, 0:52] ----------------
__global__ void k_gx(const float* __restrict__ feat, const float* __restrict__ Wih,
                     const float* __restrict__ bih) {
    int t = blockIdx.y;
    int row0 = blockIdx.x * 16;
    int tid = threadIdx.x;  // 128 = b
    __shared__ float fe[128][53];
    __shared__ float ws[16][52];
    __shared__ float bs[16];
    for (int e = 0; e < E_; e++) fe[tid][e] = feat[(tid * T_ + t) * E_ + e];
    for (int i = tid; i < 16 * E_; i += 128) {
        int r = i / E_, e = i - r * E_;
        ws[r][e] = Wih[(row0 + r) * (2 * E_) + e];
    }
    if (tid < 16) bs[tid] = bih[row0 + tid];
    __syncthreads();
    for (int r4 = 0; r4 < 16; r4 += 4) {
        float a0 = bs[r4], a1 = bs[r4 + 1], a2 = bs[r4 + 2], a3 = bs[r4 + 3];
        #pragma unroll 4
        for (int e = 0; e < E_; e++) {
            float f = fe[tid][e];
            a0 += f * ws[r4][e];
            a1 += f * ws[r4 + 1][e];
            a2 += f * ws[r4 + 2][e];
            a3 += f * ws[r4 + 3][e];
        }
        size_t base = ((size_t)t * G3_ + row0 + r4) * B_ + tid;
        g_gx[base]           = a0;
        g_gx[base + B_]      = a1;
        g_gx[base + 2 * B_]  = a2;
        g_gx[base + 3 * B_]  = a3;
    }
}

// ---------------- 6. per-step: bmi_h / argmax / outputs / bmi vector ----------------
__global__ void k_bmi(int t, int cur,
                      const float* __restrict__ Wreg, const float* __restrict__ breg,
                      const int* __restrict__ mask, const float* __restrict__ labels,
                      const float* __restrict__ embT, float* __restrict__ out) {
    int b = blockIdx.x, tid = threadIdx.x;  // 128 threads
    const float* hT = g_hT[cur];
    float p0 = 0.f, p1 = 0.f, p2 = 0.f, p3 = 0.f;
    #pragma unroll
    for (int j = tid; j < R_; j += 128) {
        float h = hT[j * B_ + b];
        p0 += h * Wreg[0 * R_ + j];
        p1 += h * Wreg[1 * R_ + j];
        p2 += h * Wreg[2 * R_ + j];
        p3 += h * Wreg[3 * R_ + j];
    }
    __shared__ float red[4][128];
    red[0][tid] = p0; red[1][tid] = p1; red[2][tid] = p2; red[3][tid] = p3;
    __syncthreads();
    __shared__ float sh_vals[4];
    __shared__ int sh_ld;
    int w = tid >> 5, lane = tid & 31;
    float sacc = red[w][lane] + red[w][lane + 32] + red[w][lane + 64] + red[w][lane + 96];
    #pragma unroll
    for (int off = 16; off; off >>= 1) sacc += __shfl_down_sync(0xffffffffu, sacc, off);
    if (lane == 0) sh_vals[w] = sacc + breg[w] + g_a[b * 4 + w];
    __syncthreads();
    if (tid == 0) {
        float v0 = sh_vals[0], v1 = sh_vals[1], v2 = sh_vals[2], v3 = sh_vals[3];
        int lbl = 0; float best = v0;
        if (v1 > best) { best = v1; lbl = 1; }
        if (v2 > best) { best = v2; lbl = 2; }
        if (v3 > best) { best = v3; lbl = 3; }
        const int REMAP[4] = {175, 176, 44, 173};
        int ld = REMAP[lbl];
        sh_ld = ld;
        out[t * B_ + b] = (float)lbl;                 // dec_output
        out[9216 + t * B_ + b] = (float)ld;           // kl_input
    }
    if (tid < 4) {
        float v = sh_vals[tid];
        out[1024 + (t * B_ + b) * 4 + tid] = sigmoidf_(v);  // dec_prob
        out[5120 + (t * B_ + b) * 4 + tid] = v;             // disc_input (bmi_h)
    }
    __syncthreads();
    if (tid < E_) {
        int m = mask[b * T_ + t];
        float bv = m ? labels[(b * T_ + t) * E_ + tid] : embT[sh_ld * E_ + tid];
        g_bmiT[tid * B_ + b] = bv;
    }
}

// ---------------- 7. big GEMM: g_gpart[ks] += W_hh · h  (FFMA2 via fma.rn.f32x2) ----------------
__device__ __forceinline__ float2 u64_f2(u64 x) {
    float2 r;
    r.x = __uint_as_float((unsigned)x);
    r.y = __uint_as_float((unsigned)(x >> 32));
    return r;
}

__global__ void __launch_bounds__(128) k_gemm(int cur) {
    int rb = blockIdx.x;             // 0..47
    int ks = blockIdx.y;             // 0..7
    int row0 = rb * RB;
    int k0 = ks * KC;
    int tid = threadIdx.x;
    int bq = tid & 31;               // b quad: covers b = 4*bq .. 4*bq+3
    int rg = tid >> 5;               // row group: rows rg*8 .. rg*8+7 within block

    __shared__ u64 W2[KT][RB];       // duplicated (w,w)
    __shared__ u64 U2[KT][B_ / 2];   // pairs of h values (b even, b odd)

    u64 acc[8][2];
    #pragma unroll
    for (int i = 0; i < 8; i++) { acc[i][0] = 0ull; acc[i][1] = 0ull; }

    const u64* hT2 = reinterpret_cast<const u64*>(g_hT[cur]);

    for (int tile = 0; tile < KC / KT; tile++) {
        int kbase = k0 + tile * KT;
        #pragma unroll
        for (int i = tid; i < KT * RB; i += 128) {
            int kk = i / RB, rr = i - kk * RB;
            W2[kk][rr] = g_Wd[(size_t)(kbase + kk) * G3_ + row0 + rr];
        }
        #pragma unroll
        for (int i = tid; i < KT * (B_ / 2); i += 128) {
            int kk = i >> 6, pp = i & 63;
            U2[kk][pp] = hT2[(size_t)(kbase + kk) * (B_ / 2) + pp];
        }
        __syncthreads();
        #pragma unroll
        for (int kk = 0; kk < KT; kk++) {
            ulonglong2 ub = *reinterpret_cast<const ulonglong2*>(&U2[kk][bq * 2]);
            const u64* wp = &W2[kk][rg * 8];
            #pragma unroll
            for (int i = 0; i < 8; i++) {
                u64 wv = wp[i];
                asm("fma.rn.f32x2 %0, %1, %2, %0;" : "+l"(acc[i][0]) : "l"(wv), "l"(ub.x));
                asm("fma.rn.f32x2 %0, %1, %2, %0;" : "+l"(acc[i][1]) : "l"(wv), "l"(ub.y));
            }
        }
        __syncthreads();
    }

    float* gp = g_gpart + (size_t)ks * G3_ * B_;
    int bb = bq * 4;
    #pragma unroll
    for (int i = 0; i < 8; i++) {
        int row = row0 + rg * 8 + i;
        float2 a0 = u64_f2(acc[i][0]);
        float2 a1 = u64_f2(acc[i][1]);
        float4 v = make_float4(a0.x, a0.y, a1.x, a1.y);
        *reinterpret_cast<float4*>(gp + (size_t)row * B_ + bb) = v;
    }
}

// ---------------- 8. gates: gather partials + bmi part, GRU nonlinearity, write h_new ----------------
__global__ void k_gates(int t, int cur, const float* __restrict__ Wih,
                        const float* __restrict__ bhh) {
    __shared__ float ws[6][52];      // bmi-part W_ih rows for 2 j's x 3 gates
    __shared__ float bm[52][128];    // bmi tile (transposed [e][b])
    int tid = threadIdx.x;           // 256
    int j0 = blockIdx.x * 2;
    for (int i = tid; i < 6 * E_; i += 256) {
        int rr = i / E_, e = i - rr * E_;
        int row = j0 + (rr & 1) + (rr >> 1) * R_;
        ws[rr][e] = Wih[row * (2 * E_) + E_ + e];
    }
    for (int i = tid; i < E_ * B_; i += 256) bm[i >> 7][i & 127] = g_bmiT[i];
    __syncthreads();

    int b = tid & 127, jj = tid >> 7;
    int j = j0 + jj;
    float s0 = 0.f, s1 = 0.f, s2 = 0.f;
    #pragma unroll 4
    for (int e = 0; e < E_; e++) {
        float bv = bm[e][b];
        s0 += bv * ws[0 + jj][e];
        s1 += bv * ws[2 + jj][e];
        s2 += bv * ws[4 + jj][e];
    }
    float ph0 = bhh[j], ph1 = bhh[j + R_], ph2 = bhh[j + 2 * R_];
    #pragma unroll
    for (int ks = 0; ks < KS; ks++) {
        const float* gp = g_gpart + (size_t)ks * G3_ * B_;
        ph0 += gp[(size_t)j * B_ + b];
        ph1 += gp[(size_t)(j + R_) * B_ + b];
        ph2 += gp[(size_t)(j + 2 * R_) * B_ + b];
    }
    size_t gxb = (size_t)t * G3_ * B_;
    float gir = g_gx[gxb + (size_t)j * B_ + b] + s0;
    float giz = g_gx[gxb + (size_t)(j + R_) * B_ + b] + s1;
    float gin = g_gx[gxb + (size_t)(j + 2 * R_) * B_ + b] + s2;
    float r = sigmoidf_(gir + ph0);
    float z = sigmoidf_(giz + ph1);
    float n = tanhf(gin + r * ph2);
    float h = g_hT[cur][j * B_ + b];
    g_hT[cur ^ 1][j * B_ + b] = (1.f - z) * n + z * h;
}

// ---------------- launcher ----------------
extern "C" void kernel_launch(void* const* d_in, const int* in_sizes, int n_in,
                              void* d_out, int out_size) {
    const float* feat   = (const float*)d_in[0];
    const float* labels = (const float*)d_in[1];
    const float* enc    = (const float*)d_in[2];
    const float* hn     = (const float*)d_in[3];
    const int*   mask   = (const int*)  d_in[4];
    const int*   elen   = (const int*)  d_in[5];
    const float* embT   = (const float*)d_in[6];
    const float* Wfc    = (const float*)d_in[7];
    const float* Wreg   = (const float*)d_in[8];
    const float* breg   = (const float*)d_in[9];
    const float* Wih    = (const float*)d_in[10];
    const float* Whh    = (const float*)d_in[11];
    const float* bih    = (const float*)d_in[12];
    const float* bhh    = (const float*)d_in[13];
    float* out = (float*)d_out;

    // prep (independent pieces; default stream keeps ordering we need)
    k_pool<<<dim3(SPLIT, B_), 128>>>(enc, elen);
    k_hT<<<64, 1024>>>(hn);
    k_wd<<<(R_ * G3_ + 511) / 512, 512>>>(Whh);
    k_gx<<<dim3(G3_ / 16, T_), 128>>>(feat, Wih, bih);
    k_reduce_a<<<B_, 128>>>(Wfc);

    for (int t = 0; t < T_; t++) {
        int cur = t & 1;
        k_bmi<<<B_, 128>>>(t, cur, Wreg, breg, mask, labels, embT, out);
        k_gemm<<<dim3(G3_ / RB, KS), 128>>>(cur);
        k_gates<<<R_ / 2, 256>>>(t, cur, Wih, bhh);
    }
}

// round 3
// speedup vs baseline: 1.2950x; 1.2950x over previous
#include <cuda_runtime.h>
#include <math.h>
#include <float.h>

typedef unsigned long long u64;

static constexpr int B_  = 128;
static constexpr int T_  = 8;
static constexpr int E_  = 52;
static constexpr int S_  = 2048;
static constexpr int R_  = 512;
static constexpr int G3_ = 1536;   // 3*R

static constexpr int SPLIT = 16;          // s-dimension split for pooling
static constexpr int SCH   = S_ / SPLIT;  // 128 rows per pooling block

// GEMM tiling
static constexpr int KS = 8;            // k-split
static constexpr int KC = R_ / KS;      // 64 k per block
static constexpr int KT = 16;           // k per smem tile
static constexpr int RB = 32;           // rows per block

// mega-kernel block ranges
static constexpr int POOL_BLOCKS = SPLIT * B_;        // 2048
static constexpr int GX_ROWTILES = G3_ / 16;          // 96
static constexpr int GX_BLOCKS   = T_ * GX_ROWTILES;  // 768
static constexpr int WD_BLOCKS   = 256;
static constexpr int HT_BLOCKS   = 64;
static constexpr int MEGA_BLOCKS = POOL_BLOCKS + GX_BLOCKS + WD_BLOCKS + HT_BLOCKS;

// step kernel ranges: 384 gemm blocks + 128 bmi blocks
static constexpr int GEMM_BLOCKS = (G3_ / RB) * KS;   // 384
static constexpr int STEP_BLOCKS = GEMM_BLOCKS + B_;  // 512

// ---------------- device scratch (no allocations allowed) ----------------
__device__ __align__(16) float g_part[B_ * SPLIT * R_];    // pooling partial maxes (4 MB)
__device__ float g_a[B_ * 4];                              // code_pool @ W_fc_pool^T
__device__ __align__(16) float g_hT[2][R_ * B_];           // hidden state, transposed [j][b], ping-pong
__device__ __align__(16) float g_bmiT[E_ * B_];            // bmi vector, transposed [e][b]
__device__ __align__(16) float g_gx[T_ * G3_ * B_];        // precomputed x-part of gi (+b_ih), [t][row][b]
__device__ __align__(16) u64   g_Wd[R_ * G3_];             // W_hh transposed + duplicated: [k][row] = (w,w)
__device__ __align__(16) float g_gpart[KS * G3_ * B_];     // k-split GEMM partials

__device__ __forceinline__ float sigmoidf_(float x) { return 1.f / (1.f + expf(-x)); }

// ================= mega prep kernel: pool | gx | wd | hT =================
__global__ void __launch_bounds__(128) k_mega(
    const float* __restrict__ enc, const int* __restrict__ enc_len,
    const float* __restrict__ feat, const float* __restrict__ Wih,
    const float* __restrict__ bih, const float* __restrict__ Whh,
    const float* __restrict__ hn)
{
    int bid = blockIdx.x;
    int tid = threadIdx.x;

    if (bid < POOL_BLOCKS) {
        // ---- ragged max-pool partial: block = (sp, b) ----
        int sp = bid & (SPLIT - 1);
        int b  = bid >> 4;                 // SPLIT = 16
        int len = enc_len[b];
        int s0 = sp * SCH;
        int s1 = min(s0 + SCH, len);
        float4 m = make_float4(-FLT_MAX, -FLT_MAX, -FLT_MAX, -FLT_MAX);
        const float4* base = reinterpret_cast<const float4*>(enc + (size_t)b * S_ * R_) + tid;
        int s = s0;
        for (; s + 4 <= s1; s += 4) {
            float4 v0 = base[(size_t)(s + 0) * (R_ / 4)];
            float4 v1 = base[(size_t)(s + 1) * (R_ / 4)];
            float4 v2 = base[(size_t)(s + 2) * (R_ / 4)];
            float4 v3 = base[(size_t)(s + 3) * (R_ / 4)];
            m.x = fmaxf(m.x, fmaxf(fmaxf(v0.x, v1.x), fmaxf(v2.x, v3.x)));
            m.y = fmaxf(m.y, fmaxf(fmaxf(v0.y, v1.y), fmaxf(v2.y, v3.y)));
            m.z = fmaxf(m.z, fmaxf(fmaxf(v0.z, v1.z), fmaxf(v2.z, v3.z)));
            m.w = fmaxf(m.w, fmaxf(fmaxf(v0.w, v1.w), fmaxf(v2.w, v3.w)));
        }
        for (; s < s1; s++) {
            float4 v = base[(size_t)s * (R_ / 4)];
            m.x = fmaxf(m.x, v.x); m.y = fmaxf(m.y, v.y);
            m.z = fmaxf(m.z, v.z); m.w = fmaxf(m.w, v.w);
        }
        reinterpret_cast<float4*>(g_part)[(b * SPLIT + sp) * (R_ / 4) + tid] = m;
        return;
    }
    bid -= POOL_BLOCKS;

    if (bid < GX_BLOCKS) {
        // ---- gx[t][row][b] = b_ih[row] + feat[b,t,:52] . W_ih[row,:52] ----
        int t    = bid / GX_ROWTILES;
        int row0 = (bid % GX_ROWTILES) * 16;
        int b    = tid;                    // 128 threads = 128 b
        __shared__ __align__(16) float ws[16][52];
        __shared__ float bs[16];
        for (int i = tid; i < 16 * E_; i += 128) {
            int r = i / E_, e = i - r * E_;
            ws[r][e] = Wih[(row0 + r) * (2 * E_) + e];
        }
        if (tid < 16) bs[tid] = bih[row0 + tid];

        // per-thread feature vector in registers (13 coalesced-per-lane LDG.128;
        // offset (b*8+t)*52 floats = multiple of 208 bytes -> 16B aligned)
        float f[52];
        const float4* fp = reinterpret_cast<const float4*>(feat + ((size_t)b * T_ + t) * E_);
        #pragma unroll
        for (int i = 0; i < 13; i++) {
            float4 v = fp[i];
            f[4*i] = v.x; f[4*i+1] = v.y; f[4*i+2] = v.z; f[4*i+3] = v.w;
        }
        __syncthreads();
        #pragma unroll 4
        for (int r = 0; r < 16; r++) {
            float acc = bs[r];
            #pragma unroll
            for (int e = 0; e < E_; e++) acc += f[e] * ws[r][e];
            g_gx[((size_t)t * G3_ + row0 + r) * B_ + b] = acc;
        }
        return;
    }
    bid -= GX_BLOCKS;

    if (bid < WD_BLOCKS) {
        // ---- duplicated/transposed W_hh: g_Wd[k*G3+row] = (w,w) ----
        for (int idx = bid * 128 + tid; idx < R_ * G3_; idx += WD_BLOCKS * 128) {
            int k = idx / G3_, row = idx - k * G3_;
            unsigned u = __float_as_uint(Whh[row * R_ + k]);
            g_Wd[idx] = ((u64)u << 32) | (u64)u;
        }
        return;
    }
    bid -= WD_BLOCKS;

    // ---- transpose h_n into g_hT[0] ----
    for (int idx = bid * 128 + tid; idx < R_ * B_; idx += HT_BLOCKS * 128) {
        int b = idx & (B_ - 1), j = idx >> 7;
        g_hT[0][j * B_ + b] = hn[b * R_ + j];
    }
}

// ---------------- reduce partials -> code_pool, then a = code @ W_fc^T ----------------
__global__ void k_reduce_a(const float* __restrict__ Wfc) {
    int b = blockIdx.x, tid = threadIdx.x;  // 128 threads
    float4 m = make_float4(-FLT_MAX, -FLT_MAX, -FLT_MAX, -FLT_MAX);
    const float4* pp = reinterpret_cast<const float4*>(g_part) + (size_t)b * SPLIT * (R_ / 4) + tid;
    #pragma unroll
    for (int sp = 0; sp < SPLIT; sp++) {
        float4 v = pp[sp * (R_ / 4)];
        m.x = fmaxf(m.x, v.x); m.y = fmaxf(m.y, v.y);
        m.z = fmaxf(m.z, v.z); m.w = fmaxf(m.w, v.w);
    }
    __shared__ __align__(16) float code[R_];
    reinterpret_cast<float4*>(code)[tid] = m;
    __syncthreads();
    float p[4] = {0.f, 0.f, 0.f, 0.f};
    int r0 = tid * 4;
    #pragma unroll
    for (int i = 0; i < 4; i++) {
        float c = code[r0 + i];
        p[0] += c * Wfc[0 * R_ + r0 + i];
        p[1] += c * Wfc[1 * R_ + r0 + i];
        p[2] += c * Wfc[2 * R_ + r0 + i];
        p[3] += c * Wfc[3 * R_ + r0 + i];
    }
    __shared__ float red[4][128];
    #pragma unroll
    for (int l = 0; l < 4; l++) red[l][tid] = p[l];
    __syncthreads();
    int w = tid >> 5, lane = tid & 31;
    float sacc = red[w][lane] + red[w][lane + 32] + red[w][lane + 64] + red[w][lane + 96];
    #pragma unroll
    for (int off = 16; off; off >>= 1) sacc += __shfl_down_sync(0xffffffffu, sacc, off);
    if (lane == 0) g_a[b * 4 + w] = sacc;
}

// ================= per-step kernel 1: big GEMM (384 blocks) | bmi (128 blocks) =================
__device__ __forceinline__ float2 u64_f2(u64 x) {
    float2 r;
    r.x = __uint_as_float((unsigned)x);
    r.y = __uint_as_float((unsigned)(x >> 32));
    return r;
}

__global__ void __launch_bounds__(128) k_step(
    int t, int cur,
    const float* __restrict__ Wreg, const float* __restrict__ breg,
    const int* __restrict__ mask, const float* __restrict__ labels,
    const float* __restrict__ embT, float* __restrict__ out)
{
    int bid = blockIdx.x;
    int tid = threadIdx.x;

    if (bid < GEMM_BLOCKS) {
        // ---- W_hh . h GEMM with fma.rn.f32x2, k-split ----
        int rb = bid % (G3_ / RB);
        int ks = bid / (G3_ / RB);
        int row0 = rb * RB;
        int k0 = ks * KC;
        int bq = tid & 31;               // b quad: b = 4*bq .. 4*bq+3
        int rg = tid >> 5;               // row group: rows rg*8 .. rg*8+7

        // NOTE: explicit 16B alignment — these are vector-loaded (LD.128);
        // the fused-kernel shared-memory layout otherwise only guarantees 8B.
        __shared__ __align__(16) u64 W2[KT][RB];
        __shared__ __align__(16) u64 U2[KT][B_ / 2];

        u64 acc[8][2];
        #pragma unroll
        for (int i = 0; i < 8; i++) { acc[i][0] = 0ull; acc[i][1] = 0ull; }

        const u64* hT2 = reinterpret_cast<const u64*>(g_hT[cur]);

        for (int tile = 0; tile < KC / KT; tile++) {
            int kbase = k0 + tile * KT;
            #pragma unroll
            for (int i = tid; i < KT * RB; i += 128) {
                int kk = i / RB, rr = i - kk * RB;
                W2[kk][rr] = g_Wd[(size_t)(kbase + kk) * G3_ + row0 + rr];
            }
            #pragma unroll
            for (int i = tid; i < KT * (B_ / 2); i += 128) {
                int kk = i >> 6, pp = i & 63;
                U2[kk][pp] = hT2[(size_t)(kbase + kk) * (B_ / 2) + pp];
            }
            __syncthreads();
            #pragma unroll
            for (int kk = 0; kk < KT; kk++) {
                ulonglong2 ub = *reinterpret_cast<const ulonglong2*>(&U2[kk][bq * 2]);
                const u64* wp = &W2[kk][rg * 8];
                #pragma unroll
                for (int i = 0; i < 8; i++) {
                    u64 wv = wp[i];
                    asm("fma.rn.f32x2 %0, %1, %2, %0;" : "+l"(acc[i][0]) : "l"(wv), "l"(ub.x));
                    asm("fma.rn.f32x2 %0, %1, %2, %0;" : "+l"(acc[i][1]) : "l"(wv), "l"(ub.y));
                }
            }
            __syncthreads();
        }

        float* gp = g_gpart + (size_t)ks * G3_ * B_;
        int bb = bq * 4;
        #pragma unroll
        for (int i = 0; i < 8; i++) {
            int row = row0 + rg * 8 + i;
            float2 a0 = u64_f2(acc[i][0]);
            float2 a1 = u64_f2(acc[i][1]);
            *reinterpret_cast<float4*>(gp + (size_t)row * B_ + bb) =
                make_float4(a0.x, a0.y, a1.x, a1.y);
        }
        return;
    }

    // ---- bmi: bmi_h / argmax / outputs / bmi vector ----
    int b = bid - GEMM_BLOCKS;
    const float* hT = g_hT[cur];
    float p0 = 0.f, p1 = 0.f, p2 = 0.f, p3 = 0.f;
    #pragma unroll
    for (int j = tid; j < R_; j += 128) {
        float h = hT[j * B_ + b];
        p0 += h * Wreg[0 * R_ + j];
        p1 += h * Wreg[1 * R_ + j];
        p2 += h * Wreg[2 * R_ + j];
        p3 += h * Wreg[3 * R_ + j];
    }
    __shared__ float red[4][128];
    red[0][tid] = p0; red[1][tid] = p1; red[2][tid] = p2; red[3][tid] = p3;
    __syncthreads();
    __shared__ float sh_vals[4];
    __shared__ int sh_ld;
    int w = tid >> 5, lane = tid & 31;
    float sacc = red[w][lane] + red[w][lane + 32] + red[w][lane + 64] + red[w][lane + 96];
    #pragma unroll
    for (int off = 16; off; off >>= 1) sacc += __shfl_down_sync(0xffffffffu, sacc, off);
    if (lane == 0) sh_vals[w] = sacc + breg[w] + g_a[b * 4 + w];
    __syncthreads();
    if (tid == 0) {
        float v0 = sh_vals[0], v1 = sh_vals[1], v2 = sh_vals[2], v3 = sh_vals[3];
        int lbl = 0; float best = v0;
        if (v1 > best) { best = v1; lbl = 1; }
        if (v2 > best) { best = v2; lbl = 2; }
        if (v3 > best) { best = v3; lbl = 3; }
        const int REMAP[4] = {175, 176, 44, 173};
        int ld = REMAP[lbl];
        sh_ld = ld;
        out[t * B_ + b] = (float)lbl;                 // dec_output
        out[9216 + t * B_ + b] = (float)ld;           // kl_input
    }
    if (tid < 4) {
        float v = sh_vals[tid];
        out[1024 + (t * B_ + b) * 4 + tid] = sigmoidf_(v);  // dec_prob
        out[5120 + (t * B_ + b) * 4 + tid] = v;             // disc_input
    }
    __syncthreads();
    if (tid < E_) {
        int m = mask[b * T_ + t];
        float bv = m ? labels[(b * T_ + t) * E_ + tid] : embT[sh_ld * E_ + tid];
        g_bmiT[tid * B_ + b] = bv;
    }
}

// ---------------- per-step kernel 2: gates (GRU nonlinearity) ----------------
__global__ void k_gates(int t, int cur, const float* __restrict__ Wih,
                        const float* __restrict__ bhh) {
    __shared__ float ws[6][52];      // bmi-part W_ih rows for 2 j's x 3 gates
    __shared__ float bm[52][128];    // bmi tile (transposed [e][b])
    int tid = threadIdx.x;           // 256
    int j0 = blockIdx.x * 2;
    for (int i = tid; i < 6 * E_; i += 256) {
        int rr = i / E_, e = i - rr * E_;
        int row = j0 + (rr & 1) + (rr >> 1) * R_;
        ws[rr][e] = Wih[row * (2 * E_) + E_ + e];
    }
    for (int i = tid; i < E_ * B_; i += 256) bm[i >> 7][i & 127] = g_bmiT[i];
    __syncthreads();

    int b = tid & 127, jj = tid >> 7;
    int j = j0 + jj;
    float s0 = 0.f, s1 = 0.f, s2 = 0.f;
    #pragma unroll 4
    for (int e = 0; e < E_; e++) {
        float bv = bm[e][b];
        s0 += bv * ws[0 + jj][e];
        s1 += bv * ws[2 + jj][e];
        s2 += bv * ws[4 + jj][e];
    }
    float ph0 = bhh[j], ph1 = bhh[j + R_], ph2 = bhh[j + 2 * R_];
    #pragma unroll
    for (int ks = 0; ks < KS; ks++) {
        const float* gp = g_gpart + (size_t)ks * G3_ * B_;
        ph0 += gp[(size_t)j * B_ + b];
        ph1 += gp[(size_t)(j + R_) * B_ + b];
        ph2 += gp[(size_t)(j + 2 * R_) * B_ + b];
    }
    size_t gxb = (size_t)t * G3_ * B_;
    float gir = g_gx[gxb + (size_t)j * B_ + b] + s0;
    float giz = g_gx[gxb + (size_t)(j + R_) * B_ + b] + s1;
    float gin = g_gx[gxb + (size_t)(j + 2 * R_) * B_ + b] + s2;
    float r = sigmoidf_(gir + ph0);
    float z = sigmoidf_(giz + ph1);
    float n = tanhf(gin + r * ph2);
    float h = g_hT[cur][j * B_ + b];
    g_hT[cur ^ 1][j * B_ + b] = (1.f - z) * n + z * h;
}

// ---------------- launcher ----------------
extern "C" void kernel_launch(void* const* d_in, const int* in_sizes, int n_in,
                              void* d_out, int out_size) {
    const float* feat   = (const float*)d_in[0];
    const float* labels = (const float*)d_in[1];
    const float* enc    = (const float*)d_in[2];
    const float* hn     = (const float*)d_in[3];
    const int*   mask   = (const int*)  d_in[4];
    const int*   elen   = (const int*)  d_in[5];
    const float* embT   = (const float*)d_in[6];
    const float* Wfc    = (const float*)d_in[7];
    const float* Wreg   = (const float*)d_in[8];
    const float* breg   = (const float*)d_in[9];
    const float* Wih    = (const float*)d_in[10];
    const float* Whh    = (const float*)d_in[11];
    const float* bih    = (const float*)d_in[12];
    const float* bhh    = (const float*)d_in[13];
    float* out = (float*)d_out;

    // one fused prep launch: pool + gx + wd + hT co-scheduled
    k_mega<<<MEGA_BLOCKS, 128>>>(enc, elen, feat, Wih, bih, Whh, hn);
    k_reduce_a<<<B_, 128>>>(Wfc);

    for (int t = 0; t < T_; t++) {
        int cur = t & 1;
        k_step<<<STEP_BLOCKS, 128>>>(t, cur, Wreg, breg, mask, labels, embT, out);
        k_gates<<<R_ / 2, 256>>>(t, cur, Wih, bhh);
    }
}